// round 8
// baseline (speedup 1.0000x reference)
#include <cuda_runtime.h>
#include <cstdint>

// Problem constants (fixed by setup_inputs)
#define BB 8
#define NN 8192
#define NPOINT 1024
#define NSAMPLE 32
#define DD 64
#define R2 0.0625f
#define OUTCH 67  // 3 + 64

#define FPS_T 512          // FPS threads per CTA
#define PPT 16             // points per thread (8 packed pairs)

using u64 = unsigned long long;
using u32 = unsigned int;

// ---- packed f32x2 helpers (per-lane IEEE RN, bit-identical to scalar RN ops)
__device__ __forceinline__ u64 pk2(float lo, float hi) {
    u64 r; asm("mov.b64 %0, {%1,%2};" : "=l"(r) : "f"(lo), "f"(hi)); return r;
}
__device__ __forceinline__ void up2(u64 v, float& lo, float& hi) {
    asm("mov.b64 {%0,%1}, %2;" : "=f"(lo), "=f"(hi) : "l"(v));
}
__device__ __forceinline__ u64 add2(u64 a, u64 b) {
    u64 r; asm("add.rn.f32x2 %0, %1, %2;" : "=l"(r) : "l"(a), "l"(b)); return r;
}
__device__ __forceinline__ u64 mul2(u64 a, u64 b) {
    u64 r; asm("mul.rn.f32x2 %0, %1, %2;" : "=l"(r) : "l"(a), "l"(b)); return r;
}

// ---------------------------------------------------------------------------
// Scratch: packed {x, y, z, |p|^2} per point (written by prep blocks fused
// into the FPS launch; consumed by ball_kernel).
// ---------------------------------------------------------------------------
__device__ float4 g_pk[BB * NN];

// ---------------------------------------------------------------------------
// Fused kernel: blocks 0..7 run FPS (one CTA per batch, 512 threads, 16
// points/thread in packed f32x2 registers). Blocks 8..135 run the pack-prep
// for ball_kernel on otherwise idle SMs.
//
// FPS per step (ONE barrier, ONE smem atomic slot):
//  - centroid fetched as pre-negated, pre-duplicated packed u64 triple from a
//    192KB smem table (3 broadcast LDS.64)
//  - packed exact distance update d = ((dx*dx + dy*dy) + dz*dz), every op RN,
//    subtraction realized as add of exact negation -> bit-identical to jnp
//  - dist kept as u32 bit patterns (nonneg floats: u32 order == float order);
//    argmax tree prefers left on '>=' => smallest k => smallest global index
//    (idx = tid + k*512) == jnp.argmax first-occurrence tie-break
//  - warp: REDUX.max(value), REDUX.min(index); lane0 posts one
//    atomicMax(u64 slot, (val<<32)|~idx)  -- max over warps = block argmax
//  - after ONE __syncthreads, every thread reads the slot with a single
//    broadcast LDS.64 (no post-barrier reduction at all)
//  - slot lifetime: 4-slot rotation; slot[(it+2)&3] is reset pre-barrier at
//    step it. Readers of that slot (step it-2) are fenced off by BAR(it-1),
//    writers (step it+2) by BAR(it+1): race-free.
// ---------------------------------------------------------------------------
__global__ void __launch_bounds__(FPS_T, 1)
fps_prep_kernel(const float* __restrict__ xyz, float* __restrict__ new_xyz) {
    const int tid = threadIdx.x;

    if (blockIdx.x >= BB) {
        // ---- prep path: pack {x,y,z,|p|^2}; |p|^2 in reference order
        int i = (blockIdx.x - BB) * FPS_T + tid;     // 0 .. BB*NN-1
        const float* p = xyz + (size_t)i * 3;
        float x = __ldg(p + 0), y = __ldg(p + 1), z = __ldg(p + 2);
        float dn = __fadd_rn(__fadd_rn(__fmul_rn(x, x), __fmul_rn(y, y)),
                             __fmul_rn(z, z));
        g_pk[i] = make_float4(x, y, z, dn);
        return;
    }

    // ---- FPS path
    extern __shared__ u64 sneg[];                 // [NN*3] = 192KB, negated dup
    __shared__ u64 aslot[4];

    const int b    = blockIdx.x;
    const int lane = tid & 31;
    const float* xb = xyz + (size_t)b * NN * 3;

    if (tid < 4) aslot[tid] = 0ull;

    // stage: load 16 points/thread; keep in packed registers AND write the
    // negated duplicated smem table
    u64 px2[8], py2[8], pz2[8];
    u32 du[PPT];
#pragma unroll
    for (int p = 0; p < 8; p++) {
        int j0 = tid + (2 * p) * FPS_T, j1 = tid + (2 * p + 1) * FPS_T;
        float x0 = __ldg(xb + j0 * 3 + 0), y0 = __ldg(xb + j0 * 3 + 1), z0 = __ldg(xb + j0 * 3 + 2);
        float x1 = __ldg(xb + j1 * 3 + 0), y1 = __ldg(xb + j1 * 3 + 1), z1 = __ldg(xb + j1 * 3 + 2);
        px2[p] = pk2(x0, x1); py2[p] = pk2(y0, y1); pz2[p] = pk2(z0, z1);
        sneg[3 * j0 + 0] = pk2(-x0, -x0);
        sneg[3 * j0 + 1] = pk2(-y0, -y0);
        sneg[3 * j0 + 2] = pk2(-z0, -z0);
        sneg[3 * j1 + 0] = pk2(-x1, -x1);
        sneg[3 * j1 + 1] = pk2(-y1, -y1);
        sneg[3 * j1 + 2] = pk2(-z1, -z1);
    }
#pragma unroll
    for (int k = 0; k < PPT; k++) du[k] = __float_as_uint(1e10f);

    __syncthreads();   // smem table + slots ready

    u64 ncx = sneg[0], ncy = sneg[1], ncz = sneg[2];   // centroid 0, negated
    float* ob = new_xyz + (size_t)b * NPOINT * 3;

    for (int it = 0; it < NPOINT; it++) {
        if (tid == 0) {   // emit un-negated centroid (sign XOR: exact)
            float lx, t0, ly, t1, lz, t2;
            up2(ncx, lx, t0); up2(ncy, ly, t1); up2(ncz, lz, t2);
            ob[it * 3 + 0] = __uint_as_float(__float_as_uint(lx) ^ 0x80000000u);
            ob[it * 3 + 1] = __uint_as_float(__float_as_uint(ly) ^ 0x80000000u);
            ob[it * 3 + 2] = __uint_as_float(__float_as_uint(lz) ^ 0x80000000u);
        }
        if (it == NPOINT - 1) break;

        // exact jnp order: d = ((dx*dx + dy*dy) + dz*dz); dist = min(dist, d)
#pragma unroll
        for (int p = 0; p < 8; p++) {
            u64 dx = add2(px2[p], ncx);
            u64 dy = add2(py2[p], ncy);
            u64 dz = add2(pz2[p], ncz);
            u64 dd = add2(add2(mul2(dx, dx), mul2(dy, dy)), mul2(dz, dz));
            float a, bq; up2(dd, a, bq);
            du[2 * p]     = min(du[2 * p],     __float_as_uint(a));
            du[2 * p + 1] = min(du[2 * p + 1], __float_as_uint(bq));
        }

        // per-thread argmax tree over 16 (ALU). '>=' keeps left -> smallest k.
        u32 v[8]; int ki[8];
#pragma unroll
        for (int i = 0; i < 8; i++) {
            v[i]  = max(du[2 * i], du[2 * i + 1]);
            ki[i] = (du[2 * i] >= du[2 * i + 1]) ? 2 * i : 2 * i + 1;
        }
#pragma unroll
        for (int i = 0; i < 4; i++) {
            ki[i] = (v[2 * i] >= v[2 * i + 1]) ? ki[2 * i] : ki[2 * i + 1];
            v[i]  = max(v[2 * i], v[2 * i + 1]);
        }
        u32 v01 = max(v[0], v[1]); int k01 = (v[0] >= v[1]) ? ki[0] : ki[1];
        u32 v23 = max(v[2], v[3]); int k23 = (v[2] >= v[3]) ? ki[2] : ki[3];
        u32 vb  = max(v01, v23);   int kk  = (v01 >= v23) ? k01 : k23;
        u32 idx = (u32)(tid + kk * FPS_T);

        // warp reduce: max value, then min index among holders of the max;
        // lane0 posts the packed key with ONE smem atomicMax (block argmax).
        u32 wmax = __reduce_max_sync(0xffffffffu, vb);
        u32 cand = (vb == wmax) ? idx : 0xffffffffu;
        u32 ci   = __reduce_min_sync(0xffffffffu, cand);
        if (lane == 0)
            atomicMax(&aslot[it & 3], ((u64)wmax << 32) | (u32)(~ci));
        if (tid == 0) aslot[(it + 2) & 3] = 0ull;   // reset 2 steps ahead
        __syncthreads();   // the ONLY barrier in the step

        // single broadcast LDS.64: winner key -> f
        const u64 key = aslot[it & 3];
        const int f = (int)(~(u32)key);

        ncx = sneg[3 * f + 0];   // broadcast LDS.64
        ncy = sneg[3 * f + 1];
        ncz = sneg[3 * f + 2];
    }
}

// ---------------------------------------------------------------------------
// Kernel 2: ball query + gather + concat. One warp per centroid, 8 warps/CTA.
// Points staged through smem as packed {x,y,z,|p|^2} float4 tiles (coalesced
// LDG.128 loads from the prep scratch, single LDS.128 per scanned point).
// Selection = first 32 indices with d<=r^2 in index order; pad with first.
// ---------------------------------------------------------------------------
#define TILE 1024
__global__ void __launch_bounds__(256)
ball_kernel(const float* __restrict__ points,
            const float* __restrict__ new_xyz, float* __restrict__ new_points) {
    __shared__ float4 sxyz[TILE];     // 16 KB
    __shared__ int sel[8][NSAMPLE];

    const int tid  = threadIdx.x;
    const int w    = tid >> 5;
    const int lane = tid & 31;
    const int gw   = blockIdx.x * 8 + w;    // centroid id
    const int b    = gw >> 10;
    const int m    = gw & (NPOINT - 1);

    const float4* pk = g_pk + (size_t)b * NN;
    const float* c  = new_xyz + ((size_t)b * NPOINT + m) * 3;
    const float sx = c[0], sy = c[1], sz = c[2];
    const float sn = __fadd_rn(__fadd_rn(__fmul_rn(sx, sx), __fmul_rn(sy, sy)),
                               __fmul_rn(sz, sz));

    int cnt = 0;
    bool done = false;
    for (int t = 0; t < NN / TILE; t++) {
        if (__syncthreads_and(done ? 1 : 0)) break;
        {   // cooperative coalesced tile load: 1024 float4, 4 per thread
            const float4* src = pk + t * TILE;
            sxyz[tid]       = __ldg(src + tid);
            sxyz[tid + 256] = __ldg(src + tid + 256);
            sxyz[tid + 512] = __ldg(src + tid + 512);
            sxyz[tid + 768] = __ldg(src + tid + 768);
        }
        __syncthreads();
        if (!done) {
            for (int base = 0; base < TILE; base += 32) {
                float4 v = sxyz[base + lane];
                // sqr = (-2*dot + |src|^2) + |dst|^2, dot = ((sx*x+sy*y)+sz*z)
                float dot = __fadd_rn(__fadd_rn(__fmul_rn(sx, v.x), __fmul_rn(sy, v.y)),
                                      __fmul_rn(sz, v.z));
                float q = __fadd_rn(__fadd_rn(__fmul_rn(-2.0f, dot), sn), v.w);
                bool ok = (q <= R2);
                unsigned msk = __ballot_sync(0xffffffffu, ok);
                if (ok) {
                    int p = cnt + __popc(msk & ((1u << lane) - 1u));
                    if (p < NSAMPLE) sel[w][p] = t * TILE + base + lane;
                }
                cnt += __popc(msk);
                if (cnt >= NSAMPLE) { done = true; break; }
            }
        }
    }
    __syncwarp();

    // pad with first qualifying index (centroid itself always qualifies)
    int cfull = cnt < NSAMPLE ? cnt : NSAMPLE;
    int first = sel[w][0];
    __syncwarp();
    if (lane >= cfull) sel[w][lane] = first;
    __syncwarp();

    float* op = new_points + ((size_t)(b * NPOINT + m)) * NSAMPLE * OUTCH;

    // centered xyz: one LDG.128 per lane's own sample
    {
        const int idx = sel[w][lane];
        float4 v = __ldg(pk + idx);
        op[lane * OUTCH + 0] = __fsub_rn(v.x, sx);
        op[lane * OUTCH + 1] = __fsub_rn(v.y, sy);
        op[lane * OUTCH + 2] = __fsub_rn(v.z, sz);
    }

    // features: per sample the warp reads one 256B row coalesced, writes 64
    // consecutive floats (2 per lane)
    const float* pb = points + (size_t)b * NN * DD;
#pragma unroll 4
    for (int s = 0; s < NSAMPLE; s++) {
        int is = sel[w][s];                       // smem broadcast
        float2 v = __ldg((const float2*)(pb + (size_t)is * DD) + lane);
        op[s * OUTCH + 3 + 2 * lane]     = v.x;
        op[s * OUTCH + 3 + 2 * lane + 1] = v.y;
    }
}

// ---------------------------------------------------------------------------
extern "C" void kernel_launch(void* const* d_in, const int* in_sizes, int n_in,
                              void* d_out, int out_size) {
    const float* xyz    = (const float*)d_in[0];
    const float* points = (const float*)d_in[1];

    float* new_xyz    = (float*)d_out;
    float* new_points = (float*)d_out + (size_t)BB * NPOINT * 3;

    const int smem = NN * 3 * sizeof(u64);   // 192 KB negated-dup table
    cudaFuncSetAttribute(fps_prep_kernel,
                         cudaFuncAttributeMaxDynamicSharedMemorySize, smem);

    // blocks 0..7: FPS (one per batch); blocks 8..135: pack-prep on idle SMs
    fps_prep_kernel<<<BB + (BB * NN) / FPS_T, FPS_T, smem>>>(xyz, new_xyz);
    ball_kernel<<<(BB * NPOINT) / 8, 256>>>(points, new_xyz, new_points);
}

// round 9
// speedup vs baseline: 1.0415x; 1.0415x over previous
#include <cuda_runtime.h>
#include <cstdint>

// Problem constants (fixed by setup_inputs)
#define BB 8
#define NN 8192
#define NPOINT 1024
#define NSAMPLE 32
#define DD 64
#define R2 0.0625f
#define OUTCH 67  // 3 + 64

#define FPS_T 512          // threads per block (uniform)
#define PPT 16             // FPS points per thread (8 packed pairs)
#define NPREP 128          // prep blocks (512 pts each)
#define BALLW 16           // warps (= centroids) per ball block
#define NBALL (BB * NPOINT / BALLW)   // 512 ball blocks
#define DYN_SMEM 196608    // 192KB for every block -> exactly 1 block/SM

using u64 = unsigned long long;
using u32 = unsigned int;

// ---- packed f32x2 helpers (per-lane IEEE RN, bit-identical to scalar RN ops)
__device__ __forceinline__ u64 pk2(float lo, float hi) {
    u64 r; asm("mov.b64 %0, {%1,%2};" : "=l"(r) : "f"(lo), "f"(hi)); return r;
}
__device__ __forceinline__ void up2(u64 v, float& lo, float& hi) {
    asm("mov.b64 {%0,%1}, %2;" : "=f"(lo), "=f"(hi) : "l"(v));
}
__device__ __forceinline__ u64 add2(u64 a, u64 b) {
    u64 r; asm("add.rn.f32x2 %0, %1, %2;" : "=l"(r) : "l"(a), "l"(b)); return r;
}
__device__ __forceinline__ u64 mul2(u64 a, u64 b) {
    u64 r; asm("mul.rn.f32x2 %0, %1, %2;" : "=l"(r) : "l"(a), "l"(b)); return r;
}

// ---------------------------------------------------------------------------
// Device scratch + producer/consumer counters (zeroed per launch by init)
// ---------------------------------------------------------------------------
__device__ float4 g_pk[BB * NN];   // packed {x,y,z,|p|^2}
__device__ int    g_progress[BB];  // FPS steps published per batch
__device__ int    g_prep_done;     // prep blocks completed

__global__ void init_kernel() {
    if (threadIdx.x < BB) g_progress[threadIdx.x] = 0;
    if (threadIdx.x == BB) g_prep_done = 0;
}

// ---------------------------------------------------------------------------
// Mega kernel: blocks 0..7 FPS (R7 scheme), 8..135 prep, 136..647 ball.
// 192KB dynamic smem per block -> one block per SM; ball never co-resides
// with FPS. Ball consumes centroids as FPS publishes them (release/acquire
// over L2), hiding the whole ball phase under the FPS critical path.
// ---------------------------------------------------------------------------
__global__ void __launch_bounds__(FPS_T, 1)
mega_kernel(const float* __restrict__ xyz, const float* __restrict__ points,
            float* __restrict__ new_xyz, float* __restrict__ new_points) {
    extern __shared__ u64 dynsmem[];
    const int bid = blockIdx.x;
    const int tid = threadIdx.x;
    const int lane = tid & 31;
    const int w    = tid >> 5;

    // =========================== PREP path ================================
    if (bid >= BB && bid < BB + NPREP) {
        int i = (bid - BB) * FPS_T + tid;        // 0 .. BB*NN-1
        const float* p = xyz + (size_t)i * 3;
        float x = __ldg(p + 0), y = __ldg(p + 1), z = __ldg(p + 2);
        float dn = __fadd_rn(__fadd_rn(__fmul_rn(x, x), __fmul_rn(y, y)),
                             __fmul_rn(z, z));
        g_pk[i] = make_float4(x, y, z, dn);
        __syncthreads();
        if (tid == 0) {
            int dummy;
            asm volatile("atom.add.release.gpu.global.s32 %0, [%1], 1;"
                         : "=r"(dummy) : "l"(&g_prep_done) : "memory");
        }
        return;
    }

    // ============================ FPS path =================================
    if (bid < BB) {
        u64* sneg = dynsmem;                      // [NN*3] negated dup table
        __shared__ u64 sw_key[2][16];

        const int b = bid;
        const float* xb = xyz + (size_t)b * NN * 3;

        u64 px2[8], py2[8], pz2[8];
        u32 du[PPT];
#pragma unroll
        for (int p = 0; p < 8; p++) {
            int j0 = tid + (2 * p) * FPS_T, j1 = tid + (2 * p + 1) * FPS_T;
            float x0 = __ldg(xb + j0 * 3 + 0), y0 = __ldg(xb + j0 * 3 + 1), z0 = __ldg(xb + j0 * 3 + 2);
            float x1 = __ldg(xb + j1 * 3 + 0), y1 = __ldg(xb + j1 * 3 + 1), z1 = __ldg(xb + j1 * 3 + 2);
            px2[p] = pk2(x0, x1); py2[p] = pk2(y0, y1); pz2[p] = pk2(z0, z1);
            sneg[3 * j0 + 0] = pk2(-x0, -x0);
            sneg[3 * j0 + 1] = pk2(-y0, -y0);
            sneg[3 * j0 + 2] = pk2(-z0, -z0);
            sneg[3 * j1 + 0] = pk2(-x1, -x1);
            sneg[3 * j1 + 1] = pk2(-y1, -y1);
            sneg[3 * j1 + 2] = pk2(-z1, -z1);
        }
#pragma unroll
        for (int k = 0; k < PPT; k++) du[k] = __float_as_uint(1e10f);

        __syncthreads();   // smem table ready

        u64 ncx = sneg[0], ncy = sneg[1], ncz = sneg[2];   // centroid 0, neg
        float* ob = new_xyz + (size_t)b * NPOINT * 3;

        for (int it = 0; it < NPOINT; it++) {
            if (tid == 0) {   // emit un-negated centroid + publish progress
                float lx, t0, ly, t1, lz, t2;
                up2(ncx, lx, t0); up2(ncy, ly, t1); up2(ncz, lz, t2);
                ob[it * 3 + 0] = __uint_as_float(__float_as_uint(lx) ^ 0x80000000u);
                ob[it * 3 + 1] = __uint_as_float(__float_as_uint(ly) ^ 0x80000000u);
                ob[it * 3 + 2] = __uint_as_float(__float_as_uint(lz) ^ 0x80000000u);
                asm volatile("st.release.gpu.global.s32 [%0], %1;"
                             :: "l"(&g_progress[b]), "r"(it + 1) : "memory");
            }
            if (it == NPOINT - 1) break;

            // exact jnp order: d = ((dx*dx+dy*dy)+dz*dz); dist = min(dist, d)
#pragma unroll
            for (int p = 0; p < 8; p++) {
                u64 dx = add2(px2[p], ncx);
                u64 dy = add2(py2[p], ncy);
                u64 dz = add2(pz2[p], ncz);
                u64 dd = add2(add2(mul2(dx, dx), mul2(dy, dy)), mul2(dz, dz));
                float a, bq; up2(dd, a, bq);
                du[2 * p]     = min(du[2 * p],     __float_as_uint(a));
                du[2 * p + 1] = min(du[2 * p + 1], __float_as_uint(bq));
            }

            // per-thread argmax tree over 16 (ALU). '>=' keeps left -> min k.
            u32 v[8]; int ki[8];
#pragma unroll
            for (int i = 0; i < 8; i++) {
                v[i]  = max(du[2 * i], du[2 * i + 1]);
                ki[i] = (du[2 * i] >= du[2 * i + 1]) ? 2 * i : 2 * i + 1;
            }
#pragma unroll
            for (int i = 0; i < 4; i++) {
                ki[i] = (v[2 * i] >= v[2 * i + 1]) ? ki[2 * i] : ki[2 * i + 1];
                v[i]  = max(v[2 * i], v[2 * i + 1]);
            }
            u32 v01 = max(v[0], v[1]); int k01 = (v[0] >= v[1]) ? ki[0] : ki[1];
            u32 v23 = max(v[2], v[3]); int k23 = (v[2] >= v[3]) ? ki[2] : ki[3];
            u32 vb  = max(v01, v23);   int kk  = (v01 >= v23) ? k01 : k23;
            u32 idx = (u32)(tid + kk * FPS_T);

            // warp: max value, then min index among holders of the max
            u32 wmax = __reduce_max_sync(0xffffffffu, vb);
            u32 cand = (vb == wmax) ? idx : 0xffffffffu;
            u32 ci   = __reduce_min_sync(0xffffffffu, cand);
            if (lane == 0) sw_key[it & 1][w] = ((u64)wmax << 32) | (u32)(~ci);
            __syncthreads();   // the ONLY barrier in the step

            // every warp reduces the 16 keys (parity buffer closes the race)
            u64 key = sw_key[it & 1][lane & 15];
            u32 khi = (u32)(key >> 32), klo = (u32)key;
            u32 mhi = __reduce_max_sync(0xffffffffu, khi);
            u32 mlo = __reduce_max_sync(0xffffffffu, (khi == mhi) ? klo : 0u);
            const int f = (int)(~mlo);

            ncx = sneg[3 * f + 0];   // broadcast LDS.64
            ncy = sneg[3 * f + 1];
            ncz = sneg[3 * f + 2];
        }
        return;
    }

    // ============================ BALL path ================================
    // block j: batch = j&7, chunk = j>>3 (batch-major interleave so wave-1
    // blocks cover the earliest centroids of every batch).
    {
        const int j     = bid - BB - NPREP;
        const int b     = j & 7;
        const int chunk = j >> 3;
        const int m     = chunk * BALLW + w;          // centroid in batch
        const int gw    = b * NPOINT + m;

        float4* sxyz = (float4*)dynsmem;              // 16KB tile
        int (*sel)[NSAMPLE] = (int(*)[NSAMPLE])(dynsmem + 2048);

        // wait until prep done AND our 16 centroids are published
        if (tid == 0) {
            const int need = chunk * BALLW + BALLW;
            int p;
            do {
                asm volatile("ld.acquire.gpu.global.s32 %0, [%1];"
                             : "=r"(p) : "l"(&g_prep_done) : "memory");
                if (p < NPREP) __nanosleep(256);
            } while (p < NPREP);
            do {
                asm volatile("ld.acquire.gpu.global.s32 %0, [%1];"
                             : "=r"(p) : "l"(&g_progress[b]) : "memory");
                if (p < need) __nanosleep(256);
            } while (p < need);
        }
        __syncthreads();

        const float4* pk = g_pk + (size_t)b * NN;
        // L1-bypassing centroid read (line may be cached stale by a neighbor)
        const float* c = new_xyz + (size_t)gw * 3;
        const float sx = __ldcg(c + 0), sy = __ldcg(c + 1), sz = __ldcg(c + 2);
        const float sn = __fadd_rn(__fadd_rn(__fmul_rn(sx, sx), __fmul_rn(sy, sy)),
                                   __fmul_rn(sz, sz));

        int cnt = 0;
        bool done = false;
        const int TILE = 1024;
        for (int t = 0; t < NN / TILE; t++) {
            if (__syncthreads_and(done ? 1 : 0)) break;
            {   // cooperative coalesced tile load: 1024 float4, 2 per thread
                const float4* src = pk + t * TILE;
                sxyz[tid]       = __ldg(src + tid);
                sxyz[tid + 512] = __ldg(src + tid + 512);
            }
            __syncthreads();
            if (!done) {
                for (int base = 0; base < TILE; base += 32) {
                    float4 v = sxyz[base + lane];
                    // sqr = (-2*dot + |src|^2) + |dst|^2
                    float dot = __fadd_rn(__fadd_rn(__fmul_rn(sx, v.x), __fmul_rn(sy, v.y)),
                                          __fmul_rn(sz, v.z));
                    float q = __fadd_rn(__fadd_rn(__fmul_rn(-2.0f, dot), sn), v.w);
                    bool ok = (q <= R2);
                    unsigned msk = __ballot_sync(0xffffffffu, ok);
                    if (ok) {
                        int p = cnt + __popc(msk & ((1u << lane) - 1u));
                        if (p < NSAMPLE) sel[w][p] = t * TILE + base + lane;
                    }
                    cnt += __popc(msk);
                    if (cnt >= NSAMPLE) { done = true; break; }
                }
            }
        }
        __syncwarp();

        // pad with first qualifying index (centroid itself always qualifies)
        int cfull = cnt < NSAMPLE ? cnt : NSAMPLE;
        int first = sel[w][0];
        __syncwarp();
        if (lane >= cfull) sel[w][lane] = first;
        __syncwarp();

        float* op = new_points + (size_t)gw * NSAMPLE * OUTCH;

        // centered xyz: one LDG.128 per lane's own sample
        {
            const int idx = sel[w][lane];
            float4 v = __ldg(pk + idx);
            op[lane * OUTCH + 0] = __fsub_rn(v.x, sx);
            op[lane * OUTCH + 1] = __fsub_rn(v.y, sy);
            op[lane * OUTCH + 2] = __fsub_rn(v.z, sz);
        }

        // features: per sample the warp reads one 256B row coalesced
        const float* pb = points + (size_t)b * NN * DD;
#pragma unroll 4
        for (int s = 0; s < NSAMPLE; s++) {
            int is = sel[w][s];                       // smem broadcast
            float2 v = __ldg((const float2*)(pb + (size_t)is * DD) + lane);
            op[s * OUTCH + 3 + 2 * lane]     = v.x;
            op[s * OUTCH + 3 + 2 * lane + 1] = v.y;
        }
    }
}

// ---------------------------------------------------------------------------
extern "C" void kernel_launch(void* const* d_in, const int* in_sizes, int n_in,
                              void* d_out, int out_size) {
    const float* xyz    = (const float*)d_in[0];
    const float* points = (const float*)d_in[1];

    float* new_xyz    = (float*)d_out;
    float* new_points = (float*)d_out + (size_t)BB * NPOINT * 3;

    cudaFuncSetAttribute(mega_kernel,
                         cudaFuncAttributeMaxDynamicSharedMemorySize, DYN_SMEM);

    init_kernel<<<1, 32>>>();
    mega_kernel<<<BB + NPREP + NBALL, FPS_T, DYN_SMEM>>>(xyz, points,
                                                         new_xyz, new_points);
}

// round 10
// speedup vs baseline: 1.3475x; 1.2939x over previous
#include <cuda_runtime.h>
#include <cstdint>

// Problem constants (fixed by setup_inputs)
#define BB 8
#define NN 8192
#define NPOINT 1024
#define NSAMPLE 32
#define DD 64
#define R2 0.0625f
#define OUTCH 67  // 3 + 64

#define FPS_T 512          // threads per block (uniform)
#define PPT 16             // FPS points per thread (8 packed pairs)
#define NPREP 128          // prep blocks (512 pts each)
#define BALLW 16           // warps (= centroids) per ball block
#define NBALL (BB * NPOINT / BALLW)   // 512 ball blocks
#define DYN_SMEM 196608    // 192KB for every block -> exactly 1 block/SM
#define PUB 16             // FPS progress publish granularity (= BALLW)

using u64 = unsigned long long;
using u32 = unsigned int;

// ---- packed f32x2 helpers (per-lane IEEE RN, bit-identical to scalar RN ops)
__device__ __forceinline__ u64 pk2(float lo, float hi) {
    u64 r; asm("mov.b64 %0, {%1,%2};" : "=l"(r) : "f"(lo), "f"(hi)); return r;
}
__device__ __forceinline__ void up2(u64 v, float& lo, float& hi) {
    asm("mov.b64 {%0,%1}, %2;" : "=f"(lo), "=f"(hi) : "l"(v));
}
__device__ __forceinline__ u64 add2(u64 a, u64 b) {
    u64 r; asm("add.rn.f32x2 %0, %1, %2;" : "=l"(r) : "l"(a), "l"(b)); return r;
}
__device__ __forceinline__ u64 mul2(u64 a, u64 b) {
    u64 r; asm("mul.rn.f32x2 %0, %1, %2;" : "=l"(r) : "l"(a), "l"(b)); return r;
}

// ---------------------------------------------------------------------------
// Device scratch + producer/consumer counters (zeroed per launch by init)
// ---------------------------------------------------------------------------
__device__ float4 g_pk[BB * NN];   // packed {x,y,z,|p|^2}
__device__ int    g_progress[BB];  // FPS steps published per batch
__device__ int    g_prep_done;     // prep blocks completed

__global__ void init_kernel() {
    if (threadIdx.x < BB) g_progress[threadIdx.x] = 0;
    if (threadIdx.x == BB) g_prep_done = 0;
}

// ---------------------------------------------------------------------------
// Mega kernel: blocks 0..7 FPS (R7 scheme), 8..135 prep, 136..647 ball.
// 192KB dynamic smem per block -> one block per SM; ball never co-resides
// with FPS. Ball consumes centroids as FPS publishes them.
// KEY FIX vs R9: progress published only every PUB=16 steps -- a gpu-scope
// release fence per step cost ~110cyc (CCTL.IVALL class); at 1/16 frequency
// the fence cost is ~7us total instead of ~115us.
// ---------------------------------------------------------------------------
__global__ void __launch_bounds__(FPS_T, 1)
mega_kernel(const float* __restrict__ xyz, const float* __restrict__ points,
            float* __restrict__ new_xyz, float* __restrict__ new_points) {
    extern __shared__ u64 dynsmem[];
    const int bid = blockIdx.x;
    const int tid = threadIdx.x;
    const int lane = tid & 31;
    const int w    = tid >> 5;

    // =========================== PREP path ================================
    if (bid >= BB && bid < BB + NPREP) {
        int i = (bid - BB) * FPS_T + tid;        // 0 .. BB*NN-1
        const float* p = xyz + (size_t)i * 3;
        float x = __ldg(p + 0), y = __ldg(p + 1), z = __ldg(p + 2);
        float dn = __fadd_rn(__fadd_rn(__fmul_rn(x, x), __fmul_rn(y, y)),
                             __fmul_rn(z, z));
        g_pk[i] = make_float4(x, y, z, dn);
        __syncthreads();
        if (tid == 0) {
            int dummy;
            asm volatile("atom.add.release.gpu.global.s32 %0, [%1], 1;"
                         : "=r"(dummy) : "l"(&g_prep_done) : "memory");
        }
        return;
    }

    // ============================ FPS path =================================
    if (bid < BB) {
        u64* sneg = dynsmem;                      // [NN*3] negated dup table
        __shared__ u64 sw_key[2][16];

        const int b = bid;
        const float* xb = xyz + (size_t)b * NN * 3;

        u64 px2[8], py2[8], pz2[8];
        u32 du[PPT];
#pragma unroll
        for (int p = 0; p < 8; p++) {
            int j0 = tid + (2 * p) * FPS_T, j1 = tid + (2 * p + 1) * FPS_T;
            float x0 = __ldg(xb + j0 * 3 + 0), y0 = __ldg(xb + j0 * 3 + 1), z0 = __ldg(xb + j0 * 3 + 2);
            float x1 = __ldg(xb + j1 * 3 + 0), y1 = __ldg(xb + j1 * 3 + 1), z1 = __ldg(xb + j1 * 3 + 2);
            px2[p] = pk2(x0, x1); py2[p] = pk2(y0, y1); pz2[p] = pk2(z0, z1);
            sneg[3 * j0 + 0] = pk2(-x0, -x0);
            sneg[3 * j0 + 1] = pk2(-y0, -y0);
            sneg[3 * j0 + 2] = pk2(-z0, -z0);
            sneg[3 * j1 + 0] = pk2(-x1, -x1);
            sneg[3 * j1 + 1] = pk2(-y1, -y1);
            sneg[3 * j1 + 2] = pk2(-z1, -z1);
        }
#pragma unroll
        for (int k = 0; k < PPT; k++) du[k] = __float_as_uint(1e10f);

        __syncthreads();   // smem table ready

        u64 ncx = sneg[0], ncy = sneg[1], ncz = sneg[2];   // centroid 0, neg
        float* ob = new_xyz + (size_t)b * NPOINT * 3;

        for (int it = 0; it < NPOINT; it++) {
            if (tid == 0) {   // emit un-negated centroid (sign XOR: exact)
                float lx, t0, ly, t1, lz, t2;
                up2(ncx, lx, t0); up2(ncy, ly, t1); up2(ncz, lz, t2);
                ob[it * 3 + 0] = __uint_as_float(__float_as_uint(lx) ^ 0x80000000u);
                ob[it * 3 + 1] = __uint_as_float(__float_as_uint(ly) ^ 0x80000000u);
                ob[it * 3 + 2] = __uint_as_float(__float_as_uint(lz) ^ 0x80000000u);
                if (((it + 1) & (PUB - 1)) == 0) {   // publish every 16 steps
                    asm volatile("st.release.gpu.global.s32 [%0], %1;"
                                 :: "l"(&g_progress[b]), "r"(it + 1) : "memory");
                }
            }
            if (it == NPOINT - 1) break;

            // exact jnp order: d = ((dx*dx+dy*dy)+dz*dz); dist = min(dist, d)
#pragma unroll
            for (int p = 0; p < 8; p++) {
                u64 dx = add2(px2[p], ncx);
                u64 dy = add2(py2[p], ncy);
                u64 dz = add2(pz2[p], ncz);
                u64 dd = add2(add2(mul2(dx, dx), mul2(dy, dy)), mul2(dz, dz));
                float a, bq; up2(dd, a, bq);
                du[2 * p]     = min(du[2 * p],     __float_as_uint(a));
                du[2 * p + 1] = min(du[2 * p + 1], __float_as_uint(bq));
            }

            // per-thread argmax tree over 16 (ALU). '>=' keeps left -> min k.
            u32 v[8]; int ki[8];
#pragma unroll
            for (int i = 0; i < 8; i++) {
                v[i]  = max(du[2 * i], du[2 * i + 1]);
                ki[i] = (du[2 * i] >= du[2 * i + 1]) ? 2 * i : 2 * i + 1;
            }
#pragma unroll
            for (int i = 0; i < 4; i++) {
                ki[i] = (v[2 * i] >= v[2 * i + 1]) ? ki[2 * i] : ki[2 * i + 1];
                v[i]  = max(v[2 * i], v[2 * i + 1]);
            }
            u32 v01 = max(v[0], v[1]); int k01 = (v[0] >= v[1]) ? ki[0] : ki[1];
            u32 v23 = max(v[2], v[3]); int k23 = (v[2] >= v[3]) ? ki[2] : ki[3];
            u32 vb  = max(v01, v23);   int kk  = (v01 >= v23) ? k01 : k23;
            u32 idx = (u32)(tid + kk * FPS_T);

            // warp: max value, then min index among holders of the max
            u32 wmax = __reduce_max_sync(0xffffffffu, vb);
            u32 cand = (vb == wmax) ? idx : 0xffffffffu;
            u32 ci   = __reduce_min_sync(0xffffffffu, cand);
            if (lane == 0) sw_key[it & 1][w] = ((u64)wmax << 32) | (u32)(~ci);
            __syncthreads();   // the ONLY barrier in the step

            // every warp reduces the 16 keys (parity buffer closes the race)
            u64 key = sw_key[it & 1][lane & 15];
            u32 khi = (u32)(key >> 32), klo = (u32)key;
            u32 mhi = __reduce_max_sync(0xffffffffu, khi);
            u32 mlo = __reduce_max_sync(0xffffffffu, (khi == mhi) ? klo : 0u);
            const int f = (int)(~mlo);

            ncx = sneg[3 * f + 0];   // broadcast LDS.64
            ncy = sneg[3 * f + 1];
            ncz = sneg[3 * f + 2];
        }
        return;
    }

    // ============================ BALL path ================================
    // block j: batch = j&7, chunk = j>>3 (batch-major interleave so wave-1
    // blocks cover the earliest centroids of every batch).
    {
        const int j     = bid - BB - NPREP;
        const int b     = j & 7;
        const int chunk = j >> 3;
        const int m     = chunk * BALLW + w;          // centroid in batch
        const int gw    = b * NPOINT + m;

        float4* sxyz = (float4*)dynsmem;              // 16KB tile
        int (*sel)[NSAMPLE] = (int(*)[NSAMPLE])(dynsmem + 2048);

        // wait until prep done AND our 16 centroids are published
        if (tid == 0) {
            const int need = chunk * BALLW + BALLW;
            int p;
            do {
                asm volatile("ld.acquire.gpu.global.s32 %0, [%1];"
                             : "=r"(p) : "l"(&g_prep_done) : "memory");
                if (p < NPREP) __nanosleep(256);
            } while (p < NPREP);
            do {
                asm volatile("ld.acquire.gpu.global.s32 %0, [%1];"
                             : "=r"(p) : "l"(&g_progress[b]) : "memory");
                if (p < need) __nanosleep(256);
            } while (p < need);
        }
        __syncthreads();

        const float4* pk = g_pk + (size_t)b * NN;
        // L1-bypassing centroid read (line may be cached stale by a neighbor)
        const float* c = new_xyz + (size_t)gw * 3;
        const float sx = __ldcg(c + 0), sy = __ldcg(c + 1), sz = __ldcg(c + 2);
        const float sn = __fadd_rn(__fadd_rn(__fmul_rn(sx, sx), __fmul_rn(sy, sy)),
                                   __fmul_rn(sz, sz));

        int cnt = 0;
        bool done = false;
        const int TILE = 1024;
        for (int t = 0; t < NN / TILE; t++) {
            if (__syncthreads_and(done ? 1 : 0)) break;
            {   // cooperative coalesced tile load: 1024 float4, 2 per thread
                const float4* src = pk + t * TILE;
                sxyz[tid]       = __ldg(src + tid);
                sxyz[tid + 512] = __ldg(src + tid + 512);
            }
            __syncthreads();
            if (!done) {
                for (int base = 0; base < TILE; base += 32) {
                    float4 v = sxyz[base + lane];
                    // sqr = (-2*dot + |src|^2) + |dst|^2
                    float dot = __fadd_rn(__fadd_rn(__fmul_rn(sx, v.x), __fmul_rn(sy, v.y)),
                                          __fmul_rn(sz, v.z));
                    float q = __fadd_rn(__fadd_rn(__fmul_rn(-2.0f, dot), sn), v.w);
                    bool ok = (q <= R2);
                    unsigned msk = __ballot_sync(0xffffffffu, ok);
                    if (ok) {
                        int p = cnt + __popc(msk & ((1u << lane) - 1u));
                        if (p < NSAMPLE) sel[w][p] = t * TILE + base + lane;
                    }
                    cnt += __popc(msk);
                    if (cnt >= NSAMPLE) { done = true; break; }
                }
            }
        }
        __syncwarp();

        // pad with first qualifying index (centroid itself always qualifies)
        int cfull = cnt < NSAMPLE ? cnt : NSAMPLE;
        int first = sel[w][0];
        __syncwarp();
        if (lane >= cfull) sel[w][lane] = first;
        __syncwarp();

        float* op = new_points + (size_t)gw * NSAMPLE * OUTCH;

        // centered xyz: one LDG.128 per lane's own sample
        {
            const int idx = sel[w][lane];
            float4 v = __ldg(pk + idx);
            op[lane * OUTCH + 0] = __fsub_rn(v.x, sx);
            op[lane * OUTCH + 1] = __fsub_rn(v.y, sy);
            op[lane * OUTCH + 2] = __fsub_rn(v.z, sz);
        }

        // features: per sample the warp reads one 256B row coalesced
        const float* pb = points + (size_t)b * NN * DD;
#pragma unroll 4
        for (int s = 0; s < NSAMPLE; s++) {
            int is = sel[w][s];                       // smem broadcast
            float2 v = __ldg((const float2*)(pb + (size_t)is * DD) + lane);
            op[s * OUTCH + 3 + 2 * lane]     = v.x;
            op[s * OUTCH + 3 + 2 * lane + 1] = v.y;
        }
    }
}

// ---------------------------------------------------------------------------
extern "C" void kernel_launch(void* const* d_in, const int* in_sizes, int n_in,
                              void* d_out, int out_size) {
    const float* xyz    = (const float*)d_in[0];
    const float* points = (const float*)d_in[1];

    float* new_xyz    = (float*)d_out;
    float* new_points = (float*)d_out + (size_t)BB * NPOINT * 3;

    cudaFuncSetAttribute(mega_kernel,
                         cudaFuncAttributeMaxDynamicSharedMemorySize, DYN_SMEM);

    init_kernel<<<1, 32>>>();
    mega_kernel<<<BB + NPREP + NBALL, FPS_T, DYN_SMEM>>>(xyz, points,
                                                         new_xyz, new_points);
}

// round 11
// speedup vs baseline: 1.4209x; 1.0544x over previous
#include <cuda_runtime.h>
#include <cstdint>

// Problem constants (fixed by setup_inputs)
#define BB 8
#define NN 8192
#define NPOINT 1024
#define NSAMPLE 32
#define DD 64
#define R2 0.0625f
#define OUTCH 67  // 3 + 64

#define FPS_T 512               // threads per block (uniform)
#define CL 4                    // cluster size = FPS CTAs per batch
#define NFPS (BB * CL)          // 32 FPS blocks
#define PTS_CTA (NN / CL)       // 2048 points per FPS CTA
#define NPREP 128               // prep blocks (512 pts each)
#define BALLW 16                // warps (= centroids) per ball block
#define NBALL (BB * NPOINT / BALLW)   // 512 ball blocks
#define DYN_SMEM 196608         // 192KB for every block -> 1 block/SM
#define PUB 16                  // FPS progress publish granularity

using u64 = unsigned long long;
using u32 = unsigned int;

// ---- packed f32x2 helpers (per-lane IEEE RN, bit-identical to scalar RN ops)
__device__ __forceinline__ u64 pk2(float lo, float hi) {
    u64 r; asm("mov.b64 %0, {%1,%2};" : "=l"(r) : "f"(lo), "f"(hi)); return r;
}
__device__ __forceinline__ void up2(u64 v, float& lo, float& hi) {
    asm("mov.b64 {%0,%1}, %2;" : "=f"(lo), "=f"(hi) : "l"(v));
}
__device__ __forceinline__ u64 add2(u64 a, u64 b) {
    u64 r; asm("add.rn.f32x2 %0, %1, %2;" : "=l"(r) : "l"(a), "l"(b)); return r;
}
__device__ __forceinline__ u64 mul2(u64 a, u64 b) {
    u64 r; asm("mul.rn.f32x2 %0, %1, %2;" : "=l"(r) : "l"(a), "l"(b)); return r;
}
__device__ __forceinline__ u32 smem_u32(const void* p) {
    u32 a;
    asm("{ .reg .u64 t; cvta.to.shared.u64 t, %1; cvt.u32.u64 %0, t; }"
        : "=r"(a) : "l"(p));
    return a;
}
__device__ __forceinline__ u32 mapa_u32(u32 a, u32 rank) {
    u32 o; asm("mapa.shared::cluster.u32 %0, %1, %2;" : "=r"(o) : "r"(a), "r"(rank));
    return o;
}
__device__ __forceinline__ u64 vlds64(u32 a) {
    u64 v; asm volatile("ld.volatile.shared.b64 %0, [%1];" : "=l"(v) : "r"(a));
    return v;
}
__device__ __forceinline__ void vsts64(u32 a, u64 v) {
    asm volatile("st.volatile.shared.b64 [%0], %1;" :: "r"(a), "l"(v) : "memory");
}
__device__ __forceinline__ void st_cluster64(u32 a, u64 v) {
    asm volatile("st.shared::cluster.b64 [%0], %1;" :: "r"(a), "l"(v) : "memory");
}

// ---------------------------------------------------------------------------
// Device scratch + producer/consumer counters (zeroed per launch by init)
// ---------------------------------------------------------------------------
__device__ float4 g_pk[BB * NN];   // packed {x,y,z,|p|^2}
__device__ int    g_progress[BB];  // FPS steps published per batch
__device__ int    g_prep_done;     // prep blocks completed

__global__ void init_kernel() {
    if (threadIdx.x < BB) g_progress[threadIdx.x] = 0;
    if (threadIdx.x == BB) g_prep_done = 0;
}

// ---------------------------------------------------------------------------
// Mega kernel, cluster size 4. Blocks 0..31: FPS (4-CTA cluster per batch,
// fence-free DSMEM key exchange). Blocks 32..159: prep. Blocks 160..671: ball.
// FPS clusters are exactly blocks 4c..4c+3 for c<8, so prep/ball clusters
// never execute cluster ops.
//
// FPS per step (ONE CTA barrier + ONE 8-byte DSMEM exchange, NO fences):
//  - each CTA owns 2048 points (4/thread, packed f32x2); dist update is
//    bit-identical to jnp (((dx*dx+dy*dy)+dz*dz), RN every op, sub = add-neg)
//  - u32-domain argmax tree ('>=' keeps left => smallest k => smallest index)
//  - warp REDUX pair -> 16 warp keys -> BAR -> warp0 reduces to the CTA key
//    (val<<32 | ~global_idx) and lane0 writes the single u64 to its own slot
//    (STS) and each peer's slot (st.shared::cluster). The key is the entire
//    payload, so no memory fence is needed; an aligned b64 store is atomic.
//  - all threads spin on ld.volatile.shared.b64 of the 4 slots (key != 0
//    guaranteed: low word = ~idx >= 0xFFFFE000); f = ~(u32)max(4 keys) --
//    max = largest value, ties -> smallest index = jnp first-occurrence.
//  - slot lifetime: 4-phase rotation. Phase (it+2)&3 is zeroed pre-BAR at
//    step it. Local readers of that phase (step it-2) finished before
//    BAR(it-1) < zero. Remote writers write it at their step it+2, which
//    causally follows consuming our step-(it+1) key, posted after our
//    BAR(it+1) > zero (BAR drains STS). Race-free; one cluster.sync at start
//    covers the initial zeroing.
// ---------------------------------------------------------------------------
__global__ void __launch_bounds__(FPS_T, 1) __cluster_dims__(CL, 1, 1)
mega_kernel(const float* __restrict__ xyz, const float* __restrict__ points,
            float* __restrict__ new_xyz, float* __restrict__ new_points) {
    extern __shared__ u64 dynsmem[];
    const int bid = blockIdx.x;
    const int tid = threadIdx.x;
    const int lane = tid & 31;
    const int w    = tid >> 5;

    // =========================== PREP path ================================
    if (bid >= NFPS && bid < NFPS + NPREP) {
        int i = (bid - NFPS) * FPS_T + tid;      // 0 .. BB*NN-1
        const float* p = xyz + (size_t)i * 3;
        float x = __ldg(p + 0), y = __ldg(p + 1), z = __ldg(p + 2);
        float dn = __fadd_rn(__fadd_rn(__fmul_rn(x, x), __fmul_rn(y, y)),
                             __fmul_rn(z, z));
        g_pk[i] = make_float4(x, y, z, dn);
        __syncthreads();
        if (tid == 0) {
            int dummy;
            asm volatile("atom.add.release.gpu.global.s32 %0, [%1], 1;"
                         : "=r"(dummy) : "l"(&g_prep_done) : "memory");
        }
        return;
    }

    // ============================ FPS path =================================
    if (bid < NFPS) {
        u64* sneg = dynsmem;                      // [NN*3] negated dup table
        __shared__ u64 wkey[2][16];
        __shared__ u64 recv[4][CL];               // [phase][rank]

        const int b       = bid >> 2;
        const u32 rank    = bid & 3;
        const int pbase   = rank * PTS_CTA;
        const float* xb   = xyz + (size_t)b * NN * 3;

        // full-batch negated table (every CTA keeps its own copy)
        for (int j = tid; j < NN; j += FPS_T) {
            float x = __ldg(xb + j * 3 + 0);
            float y = __ldg(xb + j * 3 + 1);
            float z = __ldg(xb + j * 3 + 2);
            sneg[3 * j + 0] = pk2(-x, -x);
            sneg[3 * j + 1] = pk2(-y, -y);
            sneg[3 * j + 2] = pk2(-z, -z);
        }
        // own 4 points (k = 0..3 at pbase + tid + k*512), packed by pairs
        u64 px2[2], py2[2], pz2[2];
        u32 du[4];
#pragma unroll
        for (int p = 0; p < 2; p++) {
            int j0 = pbase + tid + (2 * p) * FPS_T;
            int j1 = pbase + tid + (2 * p + 1) * FPS_T;
            px2[p] = pk2(__ldg(xb + j0 * 3 + 0), __ldg(xb + j1 * 3 + 0));
            py2[p] = pk2(__ldg(xb + j0 * 3 + 1), __ldg(xb + j1 * 3 + 1));
            pz2[p] = pk2(__ldg(xb + j0 * 3 + 2), __ldg(xb + j1 * 3 + 2));
        }
#pragma unroll
        for (int k = 0; k < 4; k++) du[k] = __float_as_uint(1e10f);

        const u32 rbase = smem_u32(&recv[0][0]);
        if (tid < 16) vsts64(rbase + tid * 8u, 0ull);   // zero all 16 slots

        // peer slot bases (3 peers)
        u32 peer[3];
#pragma unroll
        for (int i = 0; i < 3; i++)
            peer[i] = mapa_u32(rbase, (rank + 1 + i) & 3);

        __syncthreads();
        // one-time cluster rendezvous: all CTAs' recv slots zeroed before any
        // remote key write can land
        asm volatile("barrier.cluster.arrive.aligned;" ::: "memory");
        asm volatile("barrier.cluster.wait.aligned;"   ::: "memory");

        u64 ncx = sneg[0], ncy = sneg[1], ncz = sneg[2];   // centroid 0, neg
        float* ob = new_xyz + (size_t)b * NPOINT * 3;

        for (int it = 0; it < NPOINT; it++) {
            if (rank == 0 && tid == FPS_T - 1) {   // emit (warp15: off the
                float lx, t0, ly, t1, lz, t2;      //  reduce critical path)
                up2(ncx, lx, t0); up2(ncy, ly, t1); up2(ncz, lz, t2);
                ob[it * 3 + 0] = __uint_as_float(__float_as_uint(lx) ^ 0x80000000u);
                ob[it * 3 + 1] = __uint_as_float(__float_as_uint(ly) ^ 0x80000000u);
                ob[it * 3 + 2] = __uint_as_float(__float_as_uint(lz) ^ 0x80000000u);
                if (((it + 1) & (PUB - 1)) == 0) {
                    asm volatile("st.release.gpu.global.s32 [%0], %1;"
                                 :: "l"(&g_progress[b]), "r"(it + 1) : "memory");
                }
            }
            if (it == NPOINT - 1) break;

            // exact jnp order: d = ((dx*dx+dy*dy)+dz*dz); dist = min(dist, d)
#pragma unroll
            for (int p = 0; p < 2; p++) {
                u64 dx = add2(px2[p], ncx);
                u64 dy = add2(py2[p], ncy);
                u64 dz = add2(pz2[p], ncz);
                u64 dd = add2(add2(mul2(dx, dx), mul2(dy, dy)), mul2(dz, dz));
                float a, bq; up2(dd, a, bq);
                du[2 * p]     = min(du[2 * p],     __float_as_uint(a));
                du[2 * p + 1] = min(du[2 * p + 1], __float_as_uint(bq));
            }

            // argmax tree over 4 ('>=' keeps left -> smallest k on ties)
            u32 v01 = max(du[0], du[1]); int k01 = (du[0] >= du[1]) ? 0 : 1;
            u32 v23 = max(du[2], du[3]); int k23 = (du[2] >= du[3]) ? 2 : 3;
            u32 vb  = max(v01, v23);     int kk  = (v01 >= v23) ? k01 : k23;
            u32 idx = (u32)(pbase + tid + kk * FPS_T);

            // warp: max value, then min index among holders of the max
            u32 wmax = __reduce_max_sync(0xffffffffu, vb);
            u32 cand = (vb == wmax) ? idx : 0xffffffffu;
            u32 ci   = __reduce_min_sync(0xffffffffu, cand);
            if (lane == 0) wkey[it & 1][w] = ((u64)wmax << 32) | (u32)(~ci);
            if (tid == 32) {                       // zero phase it+2 (warp 1)
                u32 z = rbase + (u32)(((it + 2) & 3) * (CL * 8));
                vsts64(z, 0ull); vsts64(z + 8, 0ull);
                vsts64(z + 16, 0ull); vsts64(z + 24, 0ull);
            }
            __syncthreads();   // the ONLY CTA barrier in the step

            const u32 soff = (u32)((it & 3) * (CL * 8));
            if (w == 0) {      // designated warp: CTA key + exchange
                u64 key = wkey[it & 1][lane & 15];
                u32 khi = (u32)(key >> 32), klo = (u32)key;
                u32 mhi = __reduce_max_sync(0xffffffffu, khi);
                u32 mlo = __reduce_max_sync(0xffffffffu, (khi == mhi) ? klo : 0u);
                if (lane == 0) {
                    u64 bkey = ((u64)mhi << 32) | mlo;
                    vsts64(rbase + soff + rank * 8u, bkey);
                    st_cluster64(peer[0] + soff + rank * 8u, bkey);
                    st_cluster64(peer[1] + soff + rank * 8u, bkey);
                    st_cluster64(peer[2] + soff + rank * 8u, bkey);
                }
            }

            // all threads: poll the 4 slots (keys are provably nonzero)
            u64 k0, k1, k2, k3;
            do {
                k0 = vlds64(rbase + soff);
                k1 = vlds64(rbase + soff + 8);
                k2 = vlds64(rbase + soff + 16);
                k3 = vlds64(rbase + soff + 24);
            } while ((k0 == 0ull) | (k1 == 0ull) | (k2 == 0ull) | (k3 == 0ull));

            u64 m01 = k0 > k1 ? k0 : k1;
            u64 m23 = k2 > k3 ? k2 : k3;
            u64 km  = m01 > m23 ? m01 : m23;
            const int f = (int)(~(u32)km);

            ncx = sneg[3 * f + 0];   // broadcast LDS.64
            ncy = sneg[3 * f + 1];
            ncz = sneg[3 * f + 2];
        }
        return;
    }

    // ============================ BALL path ================================
    // block j: batch = j&7, chunk = j>>3 (batch-major interleave so early
    // blocks cover the earliest centroids of every batch).
    {
        const int j     = bid - NFPS - NPREP;
        const int b     = j & 7;
        const int chunk = j >> 3;
        const int m     = chunk * BALLW + w;          // centroid in batch
        const int gw    = b * NPOINT + m;

        float4* sxyz = (float4*)dynsmem;              // 16KB tile
        int (*sel)[NSAMPLE] = (int(*)[NSAMPLE])(dynsmem + 2048);

        // wait until prep done AND our 16 centroids are published
        if (tid == 0) {
            const int need = chunk * BALLW + BALLW;
            int p;
            do {
                asm volatile("ld.acquire.gpu.global.s32 %0, [%1];"
                             : "=r"(p) : "l"(&g_prep_done) : "memory");
                if (p < NPREP) __nanosleep(256);
            } while (p < NPREP);
            do {
                asm volatile("ld.acquire.gpu.global.s32 %0, [%1];"
                             : "=r"(p) : "l"(&g_progress[b]) : "memory");
                if (p < need) __nanosleep(256);
            } while (p < need);
        }
        __syncthreads();

        const float4* pk = g_pk + (size_t)b * NN;
        // L1-bypassing centroid read (line may be cached stale by a neighbor)
        const float* c = new_xyz + (size_t)gw * 3;
        const float sx = __ldcg(c + 0), sy = __ldcg(c + 1), sz = __ldcg(c + 2);
        const float sn = __fadd_rn(__fadd_rn(__fmul_rn(sx, sx), __fmul_rn(sy, sy)),
                                   __fmul_rn(sz, sz));

        int cnt = 0;
        bool done = false;
        const int TILE = 1024;
        for (int t = 0; t < NN / TILE; t++) {
            if (__syncthreads_and(done ? 1 : 0)) break;
            {   // cooperative coalesced tile load: 1024 float4, 2 per thread
                const float4* src = pk + t * TILE;
                sxyz[tid]       = __ldg(src + tid);
                sxyz[tid + 512] = __ldg(src + tid + 512);
            }
            __syncthreads();
            if (!done) {
                for (int base = 0; base < TILE; base += 32) {
                    float4 v = sxyz[base + lane];
                    // sqr = (-2*dot + |src|^2) + |dst|^2
                    float dot = __fadd_rn(__fadd_rn(__fmul_rn(sx, v.x), __fmul_rn(sy, v.y)),
                                          __fmul_rn(sz, v.z));
                    float q = __fadd_rn(__fadd_rn(__fmul_rn(-2.0f, dot), sn), v.w);
                    bool ok = (q <= R2);
                    unsigned msk = __ballot_sync(0xffffffffu, ok);
                    if (ok) {
                        int p = cnt + __popc(msk & ((1u << lane) - 1u));
                        if (p < NSAMPLE) sel[w][p] = t * TILE + base + lane;
                    }
                    cnt += __popc(msk);
                    if (cnt >= NSAMPLE) { done = true; break; }
                }
            }
        }
        __syncwarp();

        // pad with first qualifying index (centroid itself always qualifies)
        int cfull = cnt < NSAMPLE ? cnt : NSAMPLE;
        int first = sel[w][0];
        __syncwarp();
        if (lane >= cfull) sel[w][lane] = first;
        __syncwarp();

        float* op = new_points + (size_t)gw * NSAMPLE * OUTCH;

        // centered xyz: one LDG.128 per lane's own sample
        {
            const int idx = sel[w][lane];
            float4 v = __ldg(pk + idx);
            op[lane * OUTCH + 0] = __fsub_rn(v.x, sx);
            op[lane * OUTCH + 1] = __fsub_rn(v.y, sy);
            op[lane * OUTCH + 2] = __fsub_rn(v.z, sz);
        }

        // features: per sample the warp reads one 256B row coalesced
        const float* pb = points + (size_t)b * NN * DD;
#pragma unroll 4
        for (int s = 0; s < NSAMPLE; s++) {
            int is = sel[w][s];                       // smem broadcast
            float2 v = __ldg((const float2*)(pb + (size_t)is * DD) + lane);
            op[s * OUTCH + 3 + 2 * lane]     = v.x;
            op[s * OUTCH + 3 + 2 * lane + 1] = v.y;
        }
    }
}

// ---------------------------------------------------------------------------
extern "C" void kernel_launch(void* const* d_in, const int* in_sizes, int n_in,
                              void* d_out, int out_size) {
    const float* xyz    = (const float*)d_in[0];
    const float* points = (const float*)d_in[1];

    float* new_xyz    = (float*)d_out;
    float* new_points = (float*)d_out + (size_t)BB * NPOINT * 3;

    cudaFuncSetAttribute(mega_kernel,
                         cudaFuncAttributeMaxDynamicSharedMemorySize, DYN_SMEM);

    init_kernel<<<1, 32>>>();
    mega_kernel<<<NFPS + NPREP + NBALL, FPS_T, DYN_SMEM>>>(xyz, points,
                                                           new_xyz, new_points);
}

// round 12
// speedup vs baseline: 1.6378x; 1.1527x over previous
#include <cuda_runtime.h>
#include <cstdint>

// Problem constants (fixed by setup_inputs)
#define BB 8
#define NN 8192
#define NPOINT 1024
#define NSAMPLE 32
#define DD 64
#define R2 0.0625f
#define OUTCH 67  // 3 + 64

#define FPS_T 512               // threads per block (uniform)
#define CL 4                    // cluster size = FPS CTAs per batch
#define NFPS (BB * CL)          // 32 FPS blocks
#define PTS_CTA (NN / CL)       // 2048 points per FPS CTA
#define NPREP 128               // prep blocks (512 pts each)
#define BALLW 16                // warps (= centroids) per ball block
#define NBALL (BB * NPOINT / BALLW)   // 512 ball blocks
#define DYN_SMEM 196608         // 192KB for every block -> 1 block/SM
#define PUB 16                  // FPS progress publish granularity

using u64 = unsigned long long;
using u32 = unsigned int;

// ---- packed f32x2 helpers (per-lane IEEE RN, bit-identical to scalar RN ops)
__device__ __forceinline__ u64 pk2(float lo, float hi) {
    u64 r; asm("mov.b64 %0, {%1,%2};" : "=l"(r) : "f"(lo), "f"(hi)); return r;
}
__device__ __forceinline__ void up2(u64 v, float& lo, float& hi) {
    asm("mov.b64 {%0,%1}, %2;" : "=f"(lo), "=f"(hi) : "l"(v));
}
__device__ __forceinline__ u64 add2(u64 a, u64 b) {
    u64 r; asm("add.rn.f32x2 %0, %1, %2;" : "=l"(r) : "l"(a), "l"(b)); return r;
}
__device__ __forceinline__ u64 mul2(u64 a, u64 b) {
    u64 r; asm("mul.rn.f32x2 %0, %1, %2;" : "=l"(r) : "l"(a), "l"(b)); return r;
}
__device__ __forceinline__ u32 smem_u32(const void* p) {
    u32 a;
    asm("{ .reg .u64 t; cvta.to.shared.u64 t, %1; cvt.u32.u64 %0, t; }"
        : "=r"(a) : "l"(p));
    return a;
}
__device__ __forceinline__ u32 mapa_u32(u32 a, u32 rank) {
    u32 o; asm("mapa.shared::cluster.u32 %0, %1, %2;" : "=r"(o) : "r"(a), "r"(rank));
    return o;
}
__device__ __forceinline__ void vsts64(u32 a, u64 v) {
    asm volatile("st.volatile.shared.b64 [%0], %1;" :: "r"(a), "l"(v) : "memory");
}
__device__ __forceinline__ void st_cluster64(u32 a, u64 v) {
    asm volatile("st.shared::cluster.b64 [%0], %1;" :: "r"(a), "l"(v) : "memory");
}

// ---------------------------------------------------------------------------
// Device scratch + producer/consumer counters (zeroed per launch by init)
// ---------------------------------------------------------------------------
__device__ float4 g_pk[BB * NN];   // packed {x,y,z,|p|^2}
__device__ int    g_progress[BB];  // FPS steps published per batch
__device__ int    g_prep_done;     // prep blocks completed

__global__ void init_kernel() {
    if (threadIdx.x < BB) g_progress[threadIdx.x] = 0;
    if (threadIdx.x == BB) g_prep_done = 0;
}

// ---------------------------------------------------------------------------
// Mega kernel, cluster size 4. Blocks 0..31: FPS. 32..159: prep. 160..671:
// ball. FPS clusters are exactly blocks 4c..4c+3, so prep/ball clusters never
// execute cluster ops.
//
// FPS: BARRIER-FREE warp-key all-to-all.
//  - 64 warps per batch (16/CTA x 4 CTAs); warp (r,w) owns a u64 slot on
//    every CTA: slots[buf][r*16+w], buf = it&1.
//  - per step each warp: packed exact dist update (bit-identical to jnp),
//    u32-domain argmax ('>=' keeps left => smallest index on ties), warp
//    REDUX pair -> key = (val<<32) | ((8191-idx)<<2) | (it&3). Lane0 posts
//    the key to its own CTA (volatile STS) and the 3 peers (st.shared::
//    cluster). Single aligned 8B store = atomic; the key IS the payload, so
//    no fence is needed.
//  - each warp then polls all 64 slots of buf (1 ld.volatile.v2.u64/lane)
//    until every tag == it&3, pair-maxes, and hi/lo-REDUX-reduces to the
//    global winner. max key = max value, ties -> max (8191-idx) = smallest
//    index = jnp.argmax first-occurrence (tag bits equal across a step).
//  - slot reuse safety: buffer b's consecutive users are steps it, it+2 with
//    different tags. A writer reaches step it+2 only after polling step it+1
//    complete, which needs every warp's key(it+1), posted only after that
//    warp finished polling step it. So a slot is never overwritten unread,
//    and a stale tag can never equal the awaited tag. Slots init to tag=2
//    (first tag-2 consumer is step 2, whose buffer was rewritten at step 0);
//    one cluster.sync covers init. NO per-step barrier, NO per-step fence.
//  - emit/publish thread (rank0, last warp) free-runs: its every-16-step
//    st.release.gpu no longer stalls other warps at a barrier.
// ---------------------------------------------------------------------------
__global__ void __launch_bounds__(FPS_T, 1) __cluster_dims__(CL, 1, 1)
mega_kernel(const float* __restrict__ xyz, const float* __restrict__ points,
            float* __restrict__ new_xyz, float* __restrict__ new_points) {
    extern __shared__ u64 dynsmem[];
    const int bid = blockIdx.x;
    const int tid = threadIdx.x;
    const int lane = tid & 31;
    const int w    = tid >> 5;

    // =========================== PREP path ================================
    if (bid >= NFPS && bid < NFPS + NPREP) {
        int i = (bid - NFPS) * FPS_T + tid;      // 0 .. BB*NN-1
        const float* p = xyz + (size_t)i * 3;
        float x = __ldg(p + 0), y = __ldg(p + 1), z = __ldg(p + 2);
        float dn = __fadd_rn(__fadd_rn(__fmul_rn(x, x), __fmul_rn(y, y)),
                             __fmul_rn(z, z));
        g_pk[i] = make_float4(x, y, z, dn);
        __syncthreads();
        if (tid == 0) {
            int dummy;
            asm volatile("atom.add.release.gpu.global.s32 %0, [%1], 1;"
                         : "=r"(dummy) : "l"(&g_prep_done) : "memory");
        }
        return;
    }

    // ============================ FPS path =================================
    if (bid < NFPS) {
        u64* sneg = dynsmem;                      // [NN*3] negated dup table
        __shared__ u64 slots[2][64];              // [buf][cta*16+warp]

        const int b       = bid >> 2;
        const u32 rank    = bid & 3;
        const int pbase   = rank * PTS_CTA;
        const float* xb   = xyz + (size_t)b * NN * 3;

        // full-batch negated table (every CTA keeps its own copy)
        for (int j = tid; j < NN; j += FPS_T) {
            float x = __ldg(xb + j * 3 + 0);
            float y = __ldg(xb + j * 3 + 1);
            float z = __ldg(xb + j * 3 + 2);
            sneg[3 * j + 0] = pk2(-x, -x);
            sneg[3 * j + 1] = pk2(-y, -y);
            sneg[3 * j + 2] = pk2(-z, -z);
        }
        // own 4 points (k = 0..3 at pbase + tid + k*512), packed by pairs
        u64 px2[2], py2[2], pz2[2];
        u32 du[4];
#pragma unroll
        for (int p = 0; p < 2; p++) {
            int j0 = pbase + tid + (2 * p) * FPS_T;
            int j1 = pbase + tid + (2 * p + 1) * FPS_T;
            px2[p] = pk2(__ldg(xb + j0 * 3 + 0), __ldg(xb + j1 * 3 + 0));
            py2[p] = pk2(__ldg(xb + j0 * 3 + 1), __ldg(xb + j1 * 3 + 1));
            pz2[p] = pk2(__ldg(xb + j0 * 3 + 2), __ldg(xb + j1 * 3 + 2));
        }
#pragma unroll
        for (int k = 0; k < 4; k++) du[k] = __float_as_uint(1e10f);

        const u32 rbase = smem_u32(&slots[0][0]);
        if (tid < 64) {                    // init both buffers with tag=2
            vsts64(rbase + tid * 8u, 2ull);
            vsts64(rbase + 512u + tid * 8u, 2ull);
        }
        // peer slot bases (3 peers)
        u32 peer[3];
#pragma unroll
        for (int i = 0; i < 3; i++)
            peer[i] = mapa_u32(rbase, (rank + 1 + i) & 3);

        __syncthreads();
        // one-time cluster rendezvous: all CTAs' slots initialized before any
        // remote key write can land
        asm volatile("barrier.cluster.arrive.aligned;" ::: "memory");
        asm volatile("barrier.cluster.wait.aligned;"   ::: "memory");

        u64 ncx = sneg[0], ncy = sneg[1], ncz = sneg[2];   // centroid 0, neg
        float* ob = new_xyz + (size_t)b * NPOINT * 3;
        const bool emitter = (rank == 0) && (tid == FPS_T - 1);
        const u32 myslot = (u32)((rank * 16 + w) << 3);

        for (int it = 0; it < NPOINT; it++) {
            if (emitter) {   // emit un-negated centroid (sign XOR: exact)
                float lx, t0, ly, t1, lz, t2;
                up2(ncx, lx, t0); up2(ncy, ly, t1); up2(ncz, lz, t2);
                ob[it * 3 + 0] = __uint_as_float(__float_as_uint(lx) ^ 0x80000000u);
                ob[it * 3 + 1] = __uint_as_float(__float_as_uint(ly) ^ 0x80000000u);
                ob[it * 3 + 2] = __uint_as_float(__float_as_uint(lz) ^ 0x80000000u);
                if (((it + 1) & (PUB - 1)) == 0) {
                    asm volatile("st.release.gpu.global.s32 [%0], %1;"
                                 :: "l"(&g_progress[b]), "r"(it + 1) : "memory");
                }
            }
            if (it == NPOINT - 1) break;

            // exact jnp order: d = ((dx*dx+dy*dy)+dz*dz); dist = min(dist, d)
#pragma unroll
            for (int p = 0; p < 2; p++) {
                u64 dx = add2(px2[p], ncx);
                u64 dy = add2(py2[p], ncy);
                u64 dz = add2(pz2[p], ncz);
                u64 dd = add2(add2(mul2(dx, dx), mul2(dy, dy)), mul2(dz, dz));
                float a, bq; up2(dd, a, bq);
                du[2 * p]     = min(du[2 * p],     __float_as_uint(a));
                du[2 * p + 1] = min(du[2 * p + 1], __float_as_uint(bq));
            }

            // argmax tree over 4 ('>=' keeps left -> smallest k on ties)
            u32 v01 = max(du[0], du[1]); int k01 = (du[0] >= du[1]) ? 0 : 1;
            u32 v23 = max(du[2], du[3]); int k23 = (du[2] >= du[3]) ? 2 : 3;
            u32 vb  = max(v01, v23);     int kk  = (v01 >= v23) ? k01 : k23;
            u32 idx = (u32)(pbase + tid + kk * FPS_T);

            // warp: max value, then min index among holders of the max
            u32 wmax = __reduce_max_sync(0xffffffffu, vb);
            u32 cand = (vb == wmax) ? idx : 0xffffffffu;
            u32 ci   = __reduce_min_sync(0xffffffffu, cand);

            const u32 boff = (u32)((it & 1) << 9);
            const u32 tag  = (u32)(it & 3);
            if (lane == 0) {   // post warp key to all 4 CTAs
                u64 key = ((u64)wmax << 32)
                        | (u64)(((8191u - ci) << 2) | tag);
                vsts64(rbase + boff + myslot, key);
                st_cluster64(peer[0] + boff + myslot, key);
                st_cluster64(peer[1] + boff + myslot, key);
                st_cluster64(peer[2] + boff + myslot, key);
            }

            // poll all 64 slots (2 per lane) until every tag matches
            const u32 pa = rbase + boff + (u32)(lane << 4);
            u64 k0, k1;
            for (;;) {
                asm volatile("ld.volatile.shared.v2.u64 {%0,%1}, [%2];"
                             : "=l"(k0), "=l"(k1) : "r"(pa));
                bool ok = (((u32)k0 & 3u) == tag) & (((u32)k1 & 3u) == tag);
                if (__all_sync(0xffffffffu, ok)) break;
            }

            // reduce 64 keys: pair-max, then hi/lo REDUX trick
            u64 m = (k0 > k1) ? k0 : k1;
            u32 mhi = __reduce_max_sync(0xffffffffu, (u32)(m >> 32));
            u32 mlo = __reduce_max_sync(0xffffffffu,
                                        ((u32)(m >> 32) == mhi) ? (u32)m : 0u);
            const int f = 8191 - (int)(mlo >> 2);

            ncx = sneg[3 * f + 0];   // broadcast LDS.64
            ncy = sneg[3 * f + 1];
            ncz = sneg[3 * f + 2];
        }
        return;
    }

    // ============================ BALL path ================================
    // block j: batch = j&7, chunk = j>>3 (batch-major interleave so early
    // blocks cover the earliest centroids of every batch).
    {
        const int j     = bid - NFPS - NPREP;
        const int b     = j & 7;
        const int chunk = j >> 3;
        const int m     = chunk * BALLW + w;          // centroid in batch
        const int gw    = b * NPOINT + m;

        float4* sxyz = (float4*)dynsmem;              // 16KB tile
        int (*sel)[NSAMPLE] = (int(*)[NSAMPLE])(dynsmem + 2048);

        // wait until prep done AND our 16 centroids are published
        if (tid == 0) {
            const int need = chunk * BALLW + BALLW;
            int p;
            do {
                asm volatile("ld.acquire.gpu.global.s32 %0, [%1];"
                             : "=r"(p) : "l"(&g_prep_done) : "memory");
                if (p < NPREP) __nanosleep(256);
            } while (p < NPREP);
            do {
                asm volatile("ld.acquire.gpu.global.s32 %0, [%1];"
                             : "=r"(p) : "l"(&g_progress[b]) : "memory");
                if (p < need) __nanosleep(256);
            } while (p < need);
        }
        __syncthreads();

        const float4* pk = g_pk + (size_t)b * NN;
        // L1-bypassing centroid read (line may be cached stale by a neighbor)
        const float* c = new_xyz + (size_t)gw * 3;
        const float sx = __ldcg(c + 0), sy = __ldcg(c + 1), sz = __ldcg(c + 2);
        const float sn = __fadd_rn(__fadd_rn(__fmul_rn(sx, sx), __fmul_rn(sy, sy)),
                                   __fmul_rn(sz, sz));

        int cnt = 0;
        bool done = false;
        const int TILE = 1024;
        for (int t = 0; t < NN / TILE; t++) {
            if (__syncthreads_and(done ? 1 : 0)) break;
            {   // cooperative coalesced tile load: 1024 float4, 2 per thread
                const float4* src = pk + t * TILE;
                sxyz[tid]       = __ldg(src + tid);
                sxyz[tid + 512] = __ldg(src + tid + 512);
            }
            __syncthreads();
            if (!done) {
                for (int base = 0; base < TILE; base += 32) {
                    float4 v = sxyz[base + lane];
                    // sqr = (-2*dot + |src|^2) + |dst|^2
                    float dot = __fadd_rn(__fadd_rn(__fmul_rn(sx, v.x), __fmul_rn(sy, v.y)),
                                          __fmul_rn(sz, v.z));
                    float q = __fadd_rn(__fadd_rn(__fmul_rn(-2.0f, dot), sn), v.w);
                    bool ok = (q <= R2);
                    unsigned msk = __ballot_sync(0xffffffffu, ok);
                    if (ok) {
                        int p = cnt + __popc(msk & ((1u << lane) - 1u));
                        if (p < NSAMPLE) sel[w][p] = t * TILE + base + lane;
                    }
                    cnt += __popc(msk);
                    if (cnt >= NSAMPLE) { done = true; break; }
                }
            }
        }
        __syncwarp();

        // pad with first qualifying index (centroid itself always qualifies)
        int cfull = cnt < NSAMPLE ? cnt : NSAMPLE;
        int first = sel[w][0];
        __syncwarp();
        if (lane >= cfull) sel[w][lane] = first;
        __syncwarp();

        float* op = new_points + (size_t)gw * NSAMPLE * OUTCH;

        // centered xyz: one LDG.128 per lane's own sample
        {
            const int idx = sel[w][lane];
            float4 v = __ldg(pk + idx);
            op[lane * OUTCH + 0] = __fsub_rn(v.x, sx);
            op[lane * OUTCH + 1] = __fsub_rn(v.y, sy);
            op[lane * OUTCH + 2] = __fsub_rn(v.z, sz);
        }

        // features: per sample the warp reads one 256B row coalesced
        const float* pb = points + (size_t)b * NN * DD;
#pragma unroll 4
        for (int s = 0; s < NSAMPLE; s++) {
            int is = sel[w][s];                       // smem broadcast
            float2 v = __ldg((const float2*)(pb + (size_t)is * DD) + lane);
            op[s * OUTCH + 3 + 2 * lane]     = v.x;
            op[s * OUTCH + 3 + 2 * lane + 1] = v.y;
        }
    }
}

// ---------------------------------------------------------------------------
extern "C" void kernel_launch(void* const* d_in, const int* in_sizes, int n_in,
                              void* d_out, int out_size) {
    const float* xyz    = (const float*)d_in[0];
    const float* points = (const float*)d_in[1];

    float* new_xyz    = (float*)d_out;
    float* new_points = (float*)d_out + (size_t)BB * NPOINT * 3;

    cudaFuncSetAttribute(mega_kernel,
                         cudaFuncAttributeMaxDynamicSharedMemorySize, DYN_SMEM);

    init_kernel<<<1, 32>>>();
    mega_kernel<<<NFPS + NPREP + NBALL, FPS_T, DYN_SMEM>>>(xyz, points,
                                                           new_xyz, new_points);
}